// round 1
// baseline (speedup 1.0000x reference)
#include <cuda_runtime.h>

// Problem dims
#define B_  64
#define T_  2048
#define IN_ 256
#define H_  512
#define C_  128

// Scan config: 16 clusters x 8 CTAs, 4 batches/cluster, 64 H-rows/CTA
#define CLUSTER_S 8
#define JS        64      // H_/CLUSTER_S rows of W_hh per CTA
#define GBATCH    4       // batches per cluster
#define WPAD      516     // padded row stride (words) -> conflict-free LDS128
#define SCAN_THREADS 256

// Scratch ping-pong buffers (device globals: allocation-free)
__device__ float g_bufA[(size_t)B_ * T_ * H_];
__device__ float g_bufB[(size_t)B_ * T_ * H_];

static __device__ __forceinline__ unsigned smem_u32(const void* p) {
    unsigned r;
    asm("{ .reg .u64 t; cvta.to.shared.u64 t, %1; cvt.u32.u64 %0, t; }"
        : "=r"(r) : "l"(p));
    return r;
}

// ---------------------------------------------------------------------------
// Recurrent scan: h_t = relu(pre_t + W_hh @ h_{t-1}), batch-parallel across
// clusters, H split across the 8 CTAs of a cluster. W_hh slice lives in SMEM;
// h replicated per-CTA in SMEM, exchanged via DSMEM stores + cluster barrier.
// ---------------------------------------------------------------------------
__global__ void __launch_bounds__(SCAN_THREADS, 1) __cluster_dims__(CLUSTER_S, 1, 1)
scan_kernel(const float* __restrict__ W_hh, const float* pre, float* hout)
{
    extern __shared__ float sm[];
    float* Ws = sm;                         // JS x WPAD
    float* Hs = sm + JS * WPAD;             // 2 x GBATCH x WPAD (double buffer)

    const int tid  = threadIdx.x;
    const int rank = blockIdx.x & (CLUSTER_S - 1);
    const int bg   = blockIdx.x >> 3;
    const int bl   = tid & 3;               // batch within cluster group
    const int jl   = tid >> 2;              // local output row 0..63
    const int jg   = rank * JS + jl;        // global h index this thread owns
    const int b    = bg * GBATCH + bl;      // global batch

    // Load this CTA's 64x512 slice of W_hh into padded SMEM (once).
    for (int i = tid; i < JS * (H_ / 4); i += SCAN_THREADS) {
        int r  = i / (H_ / 4);
        int c4 = (i % (H_ / 4)) * 4;
        float4 v = *reinterpret_cast<const float4*>(
            &W_hh[(size_t)(rank * JS + r) * H_ + c4]);
        *reinterpret_cast<float4*>(&Ws[r * WPAD + c4]) = v;
    }
    // h_0 = 0 (both buffers)
    for (int i = tid; i < 2 * GBATCH * WPAD; i += SCAN_THREADS) Hs[i] = 0.f;
    __syncthreads();
    asm volatile("barrier.cluster.arrive.aligned;" ::: "memory");
    asm volatile("barrier.cluster.wait.aligned;"   ::: "memory");

    const float* preP  = pre  + (size_t)b * T_ * H_ + jg;
    float*       houtP = hout + (size_t)b * T_ * H_ + jg;
    const float* wrow  = Ws + jl * WPAD;

    // local SMEM byte-addresses of Hs[buf][bl][jg] for DSMEM replication
    unsigned hdst[2];
    hdst[0] = smem_u32(&Hs[(0 * GBATCH + bl) * WPAD + jg]);
    hdst[1] = smem_u32(&Hs[(1 * GBATCH + bl) * WPAD + jg]);

    int cur = 0;
    for (int t = 0; t < T_; ++t) {
        float pv = *preP;                   // prefetch pre (hidden under dot)
        const float* hrow = Hs + (cur * GBATCH + bl) * WPAD;

        float4 acc = make_float4(0.f, 0.f, 0.f, 0.f);
        #pragma unroll 16
        for (int k = 0; k < H_; k += 4) {
            float4 w = *reinterpret_cast<const float4*>(wrow + k);
            float4 h = *reinterpret_cast<const float4*>(hrow + k);
            acc.x += w.x * h.x;
            acc.y += w.y * h.y;
            acc.z += w.z * h.z;
            acc.w += w.w * h.w;
        }
        float val = fmaxf((acc.x + acc.y) + (acc.z + acc.w) + pv, 0.f);

        // replicate h[b][jg] into every cluster CTA's next buffer
        const int nxt = cur ^ 1;
        unsigned laddr = hdst[nxt];
        unsigned uval  = __float_as_uint(val);
        #pragma unroll
        for (int r = 0; r < CLUSTER_S; ++r) {
            unsigned raddr;
            asm volatile("mapa.shared::cluster.u32 %0, %1, %2;"
                         : "=r"(raddr) : "r"(laddr), "r"(r));
            asm volatile("st.shared::cluster.u32 [%0], %1;"
                         :: "r"(raddr), "r"(uval) : "memory");
        }
        *houtP = val;                        // stream h_t to global
        preP  += H_;
        houtP += H_;

        asm volatile("barrier.cluster.arrive.aligned;" ::: "memory");
        asm volatile("barrier.cluster.wait.aligned;"   ::: "memory");
        cur = nxt;
    }
}

// ---------------------------------------------------------------------------
// C[M,N] = A[M,K] @ Bw[N,K]^T + bias1[N] + bias2[N]   (fp32 tiled SGEMM)
// BM=128, BN=128, BK=8, 256 threads, 8x8 thread tile.
// ---------------------------------------------------------------------------
#define BM 128
#define BN 128
#define BK 8
#define TM 8
#define TN 8

__global__ void __launch_bounds__(256)
sgemm_bias_kernel(const float* __restrict__ A, const float* __restrict__ Bw,
                  const float* __restrict__ bias1, const float* __restrict__ bias2,
                  float* __restrict__ C, int M, int N, int K)
{
    __shared__ float As[BK][BM];
    __shared__ float Bs[BK][BN];

    const int tid  = threadIdx.x;
    const int bm   = blockIdx.x * BM;
    const int bn   = blockIdx.y * BN;
    const int lrow = tid >> 1;          // 0..127
    const int lc   = (tid & 1) * 4;     // 0 or 4
    const int tx   = tid & 15;
    const int ty   = tid >> 4;

    float acc[TM][TN] = {};

    for (int k0 = 0; k0 < K; k0 += BK) {
        float4 av = *reinterpret_cast<const float4*>(
            &A[(size_t)(bm + lrow) * K + k0 + lc]);
        float4 bv = *reinterpret_cast<const float4*>(
            &Bw[(size_t)(bn + lrow) * K + k0 + lc]);
        __syncthreads();
        As[lc + 0][lrow] = av.x; As[lc + 1][lrow] = av.y;
        As[lc + 2][lrow] = av.z; As[lc + 3][lrow] = av.w;
        Bs[lc + 0][lrow] = bv.x; Bs[lc + 1][lrow] = bv.y;
        Bs[lc + 2][lrow] = bv.z; Bs[lc + 3][lrow] = bv.w;
        __syncthreads();

        #pragma unroll
        for (int kk = 0; kk < BK; ++kk) {
            float ra[TM], rb[TN];
            #pragma unroll
            for (int i = 0; i < TM; ++i) ra[i] = As[kk][ty * TM + i];
            #pragma unroll
            for (int j = 0; j < TN; ++j) rb[j] = Bs[kk][tx * TN + j];
            #pragma unroll
            for (int i = 0; i < TM; ++i)
                #pragma unroll
                for (int j = 0; j < TN; ++j)
                    acc[i][j] += ra[i] * rb[j];
        }
    }

    #pragma unroll
    for (int i = 0; i < TM; ++i) {
        const size_t row = (size_t)(bm + ty * TM + i) * N;
        #pragma unroll
        for (int j = 0; j < TN; ++j) {
            const int col = bn + tx * TN + j;
            C[row + col] = acc[i][j] + bias1[col] + bias2[col];
        }
    }
}

// ---------------------------------------------------------------------------
// out[b,c] = h1[b, T-1, :] . fc_w[c, :] + fc_b[c]
// ---------------------------------------------------------------------------
__global__ void __launch_bounds__(C_)
fc_kernel(const float* __restrict__ h, const float* __restrict__ fw,
          const float* __restrict__ fb, float* __restrict__ out)
{
    __shared__ float hv[H_];
    const int b = blockIdx.x;
    const int c = threadIdx.x;
    for (int k = c; k < H_; k += C_)
        hv[k] = h[((size_t)b * T_ + (T_ - 1)) * H_ + k];
    __syncthreads();

    const float* w = fw + (size_t)c * H_;
    float acc = 0.f;
    #pragma unroll 8
    for (int k = 0; k < H_; k += 4) {
        float4 wv = *reinterpret_cast<const float4*>(w + k);
        acc += wv.x * hv[k] + wv.y * hv[k + 1] + wv.z * hv[k + 2] + wv.w * hv[k + 3];
    }
    out[b * C_ + c] = acc + fb[c];
}

// ---------------------------------------------------------------------------
extern "C" void kernel_launch(void* const* d_in, const int* in_sizes, int n_in,
                              void* d_out, int out_size)
{
    const float* x     = (const float*)d_in[0];
    const float* W_ih0 = (const float*)d_in[1];
    const float* W_hh0 = (const float*)d_in[2];
    const float* b_ih0 = (const float*)d_in[3];
    const float* b_hh0 = (const float*)d_in[4];
    const float* W_ih1 = (const float*)d_in[5];
    const float* W_hh1 = (const float*)d_in[6];
    const float* b_ih1 = (const float*)d_in[7];
    const float* b_hh1 = (const float*)d_in[8];
    const float* fc_w  = (const float*)d_in[9];
    const float* fc_b  = (const float*)d_in[10];
    float* out = (float*)d_out;

    float *bufA, *bufB;
    cudaGetSymbolAddress((void**)&bufA, g_bufA);
    cudaGetSymbolAddress((void**)&bufB, g_bufB);

    const int scan_smem = (JS * WPAD + 2 * GBATCH * WPAD) * (int)sizeof(float);
    cudaFuncSetAttribute(scan_kernel,
                         cudaFuncAttributeMaxDynamicSharedMemorySize, scan_smem);

    const int M = B_ * T_;
    dim3 gemm_grid(M / BM, H_ / BN);

    // pre0 = x @ W_ih0^T + b_ih0 + b_hh0
    sgemm_bias_kernel<<<gemm_grid, 256>>>(x, W_ih0, b_ih0, b_hh0, bufA,
                                          M, H_, IN_);
    // layer 0 scan: bufA(pre) -> bufB(h0)
    scan_kernel<<<dim3(16 * CLUSTER_S), SCAN_THREADS, scan_smem>>>(W_hh0, bufA, bufB);
    // pre1 = h0 @ W_ih1^T + b_ih1 + b_hh1
    sgemm_bias_kernel<<<gemm_grid, 256>>>(bufB, W_ih1, b_ih1, b_hh1, bufA,
                                          M, H_, H_);
    // layer 1 scan: bufA(pre) -> bufA(h1, in-place)
    scan_kernel<<<dim3(16 * CLUSTER_S), SCAN_THREADS, scan_smem>>>(W_hh1, bufA, bufA);
    // out = h1[:, -1, :] @ fc_w^T + fc_b
    fc_kernel<<<B_, C_>>>(bufA, fc_w, fc_b, out);
}

// round 2
// speedup vs baseline: 1.7857x; 1.7857x over previous
#include <cuda_runtime.h>

// Problem dims
#define B_  64
#define T_  2048
#define IN_ 256
#define H_  512
#define C_  128

// Scan config: 16 clusters x 8 CTAs, 4 batches/cluster, 64 H-rows/CTA
#define CLUSTER_S 8
#define JS        64      // H_/CLUSTER_S rows of W_hh per CTA
#define GBATCH    4       // batches per cluster
#define KC        4       // k-chunks per row
#define KPT       128     // k elements per thread (H_/KC)
#define SCAN_THREADS 256

// Scratch ping-pong buffers (device globals: allocation-free)
__device__ float g_bufA[(size_t)B_ * T_ * H_];
__device__ float g_bufB[(size_t)B_ * T_ * H_];

static __device__ __forceinline__ unsigned smem_u32(const void* p) {
    unsigned r;
    asm("{ .reg .u64 t; cvta.to.shared.u64 t, %1; cvt.u32.u64 %0, t; }"
        : "=r"(r) : "l"(p));
    return r;
}

// packed fp32x2 FMA: d = a*b + d   (2 FMAs / inst — ptxas won't emit from C++)
static __device__ __forceinline__ void ffma2(unsigned long long& d,
                                             unsigned long long a,
                                             unsigned long long b) {
    asm("fma.rn.f32x2 %0, %1, %2, %0;" : "+l"(d) : "l"(a), "l"(b));
}

static __device__ __forceinline__ float hadd_pair2(unsigned long long a,
                                                   unsigned long long b) {
    unsigned long long s;
    asm("add.rn.f32x2 %0, %1, %2;" : "=l"(s) : "l"(a), "l"(b));
    float lo = __uint_as_float((unsigned)(s & 0xffffffffull));
    float hi = __uint_as_float((unsigned)(s >> 32));
    return lo + hi;
}

static __device__ __forceinline__ unsigned long long dupf(float f) {
    unsigned long long r;
    asm("mov.b64 %0, {%1, %1};" : "=l"(r) : "f"(f));
    return r;
}

// ---------------------------------------------------------------------------
// Recurrent scan: h_t = relu(pre_t + W_hh @ h_{t-1}).
// 16 clusters x 8 CTAs. Each CTA: 64 rows of W_hh held in REGISTERS
// (thread (kc,j) holds W[j][kc*128 .. kc*128+127] as 64 packed f32x2 regs).
// h lives in SMEM (double-buffered), read as warp-uniform broadcast LDS.128,
// multiplied with fma.rn.f32x2. Cross-kc reduction via SMEM, then each
// (j,b) value is replicated to all 8 cluster CTAs via st.shared::cluster.
// ---------------------------------------------------------------------------
__global__ void __launch_bounds__(SCAN_THREADS, 1) __cluster_dims__(CLUSTER_S, 1, 1)
scan_kernel(const float* __restrict__ W_hh, const float* __restrict__ pre,
            float* __restrict__ hout)
{
    __shared__ float Hs[2][GBATCH][H_];          // 16 KB
    __shared__ float red[KC][JS][GBATCH];        // 4 KB

    const int tid  = threadIdx.x;
    const int rank = blockIdx.x & (CLUSTER_S - 1);
    const int bg   = blockIdx.x >> 3;

    // partial-producer identity
    const int kc = tid >> 6;            // 0..3
    const int j  = tid & 63;            // 0..63
    // reducer identity
    const int j2   = tid >> 2;          // 0..63
    const int b2   = tid & 3;           // 0..3
    const int jg2  = rank * JS + j2;
    const int bred = bg * GBATCH + b2;

    // Load this thread's W slice into registers (64 packed f32x2 = 128 fp32)
    unsigned long long w[KPT / 2];
    {
        const float* wsrc = W_hh + (size_t)(rank * JS + j) * H_ + kc * KPT;
        #pragma unroll
        for (int i = 0; i < KPT / 2; i++)
            w[i] = *reinterpret_cast<const unsigned long long*>(wsrc + 2 * i);
    }

    // h_0 = 0 in both buffers
    for (int i = tid; i < 2 * GBATCH * H_; i += SCAN_THREADS)
        (&Hs[0][0][0])[i] = 0.f;

    // Precompute the 16 remote SMEM addresses (2 buffers x 8 ranks)
    unsigned loc0 = smem_u32(&Hs[0][b2][jg2]);
    unsigned loc1 = smem_u32(&Hs[1][b2][jg2]);
    unsigned rem[2][CLUSTER_S];
    #pragma unroll
    for (int r = 0; r < CLUSTER_S; r++) {
        asm("mapa.shared::cluster.u32 %0, %1, %2;" : "=r"(rem[0][r]) : "r"(loc0), "r"(r));
        asm("mapa.shared::cluster.u32 %0, %1, %2;" : "=r"(rem[1][r]) : "r"(loc1), "r"(r));
    }

    __syncthreads();
    asm volatile("barrier.cluster.arrive.aligned;" ::: "memory");
    asm volatile("barrier.cluster.wait.aligned;"   ::: "memory");

    const float* preP  = pre  + ((size_t)bred * T_) * H_ + jg2;
    float*       houtP = hout + ((size_t)bred * T_) * H_ + jg2;

    float pv = *preP;                   // pre for t=0 (prefetched)
    int cur = 0;

    #pragma unroll 1
    for (int t = 0; t < T_; ++t) {
        // ---- partial dot products (issue-bound: FFMA2 + broadcast LDS128)
        float part[GBATCH];
        #pragma unroll
        for (int b = 0; b < GBATCH; b++) {
            const ulonglong2* hr =
                reinterpret_cast<const ulonglong2*>(&Hs[cur][b][kc * KPT]);
            unsigned long long a0 = 0ull, a1 = 0ull;
            #pragma unroll
            for (int i = 0; i < KPT / 4; i++) {
                ulonglong2 hv = hr[i];          // warp-uniform broadcast
                ffma2(a0, w[2 * i],     hv.x);
                ffma2(a1, w[2 * i + 1], hv.y);
            }
            part[b] = hadd_pair2(a0, a1);
        }
        *reinterpret_cast<float4*>(&red[kc][j][0]) =
            make_float4(part[0], part[1], part[2], part[3]);
        __syncthreads();

        // ---- cross-kc reduction + bias + relu (reducer role)
        float s = red[0][j2][b2] + red[1][j2][b2]
                + red[2][j2][b2] + red[3][j2][b2] + pv;
        float val = fmaxf(s, 0.f);

        // ---- replicate h[b][jg] into every cluster CTA's next buffer
        const int nxt = cur ^ 1;
        unsigned uval = __float_as_uint(val);
        #pragma unroll
        for (int r = 0; r < CLUSTER_S; ++r)
            asm volatile("st.shared::cluster.u32 [%0], %1;"
                         :: "r"(rem[nxt][r]), "r"(uval) : "memory");
        asm volatile("barrier.cluster.arrive.aligned;" ::: "memory");

        // overlapped with barrier: stream h_t out, prefetch next pre
        houtP[(size_t)t * H_] = val;
        if (t + 1 < T_) pv = preP[(size_t)(t + 1) * H_];

        asm volatile("barrier.cluster.wait.aligned;" ::: "memory");
        cur = nxt;
    }
}

// ---------------------------------------------------------------------------
// C[M,N] = A[M,K] @ Bw[N,K]^T + bias1[N] + bias2[N]   (fp32 tiled SGEMM)
// BM=128, BN=128, BK=8, 256 threads, 8x8 thread tile, f32x2 inner product.
// ---------------------------------------------------------------------------
#define BM 128
#define BN 128
#define BK 8
#define TM 8
#define TN 8

__global__ void __launch_bounds__(256)
sgemm_bias_kernel(const float* __restrict__ A, const float* __restrict__ Bw,
                  const float* __restrict__ bias1, const float* __restrict__ bias2,
                  float* __restrict__ C, int M, int N, int K)
{
    __shared__ float As[BK][BM];
    __shared__ float Bs[BK][BN];

    const int tid  = threadIdx.x;
    const int bm   = blockIdx.x * BM;
    const int bn   = blockIdx.y * BN;
    const int lrow = tid >> 1;          // 0..127
    const int lc   = (tid & 1) * 4;     // 0 or 4
    const int tx   = tid & 15;
    const int ty   = tid >> 4;

    // acc2[i2][j]: packed pair over rows (2*i2, 2*i2+1), column j
    unsigned long long acc2[TM / 2][TN];
    #pragma unroll
    for (int i = 0; i < TM / 2; i++)
        #pragma unroll
        for (int jj = 0; jj < TN; jj++) acc2[i][jj] = 0ull;

    for (int k0 = 0; k0 < K; k0 += BK) {
        float4 av = *reinterpret_cast<const float4*>(
            &A[(size_t)(bm + lrow) * K + k0 + lc]);
        float4 bv = *reinterpret_cast<const float4*>(
            &Bw[(size_t)(bn + lrow) * K + k0 + lc]);
        __syncthreads();
        As[lc + 0][lrow] = av.x; As[lc + 1][lrow] = av.y;
        As[lc + 2][lrow] = av.z; As[lc + 3][lrow] = av.w;
        Bs[lc + 0][lrow] = bv.x; Bs[lc + 1][lrow] = bv.y;
        Bs[lc + 2][lrow] = bv.z; Bs[lc + 3][lrow] = bv.w;
        __syncthreads();

        #pragma unroll
        for (int kk = 0; kk < BK; ++kk) {
            ulonglong2 raA = *reinterpret_cast<const ulonglong2*>(&As[kk][ty * TM]);
            ulonglong2 raB = *reinterpret_cast<const ulonglong2*>(&As[kk][ty * TM + 4]);
            float4 rb0 = *reinterpret_cast<const float4*>(&Bs[kk][tx * TN]);
            float4 rb1 = *reinterpret_cast<const float4*>(&Bs[kk][tx * TN + 4]);
            unsigned long long ra[4] = { raA.x, raA.y, raB.x, raB.y };
            unsigned long long rbb[8];
            rbb[0] = dupf(rb0.x); rbb[1] = dupf(rb0.y);
            rbb[2] = dupf(rb0.z); rbb[3] = dupf(rb0.w);
            rbb[4] = dupf(rb1.x); rbb[5] = dupf(rb1.y);
            rbb[6] = dupf(rb1.z); rbb[7] = dupf(rb1.w);
            #pragma unroll
            for (int i2 = 0; i2 < 4; ++i2)
                #pragma unroll
                for (int jj = 0; jj < TN; ++jj)
                    ffma2(acc2[i2][jj], ra[i2], rbb[jj]);
        }
    }

    #pragma unroll
    for (int i2 = 0; i2 < TM / 2; ++i2) {
        const size_t row0 = (size_t)(bm + ty * TM + 2 * i2) * N;
        const size_t row1 = row0 + N;
        #pragma unroll
        for (int jj = 0; jj < TN; ++jj) {
            const int col = bn + tx * TN + jj;
            float lo = __uint_as_float((unsigned)(acc2[i2][jj] & 0xffffffffull));
            float hi = __uint_as_float((unsigned)(acc2[i2][jj] >> 32));
            float bsum = bias1[col] + bias2[col];
            C[row0 + col] = lo + bsum;
            C[row1 + col] = hi + bsum;
        }
    }
}

// ---------------------------------------------------------------------------
// out[b,c] = h1[b, T-1, :] . fc_w[c, :] + fc_b[c]
// ---------------------------------------------------------------------------
__global__ void __launch_bounds__(C_)
fc_kernel(const float* __restrict__ h, const float* __restrict__ fw,
          const float* __restrict__ fb, float* __restrict__ out)
{
    __shared__ float hv[H_];
    const int b = blockIdx.x;
    const int c = threadIdx.x;
    for (int k = c; k < H_; k += C_)
        hv[k] = h[((size_t)b * T_ + (T_ - 1)) * H_ + k];
    __syncthreads();

    const float* w = fw + (size_t)c * H_;
    float acc = 0.f;
    #pragma unroll 8
    for (int k = 0; k < H_; k += 4) {
        float4 wv = *reinterpret_cast<const float4*>(w + k);
        acc += wv.x * hv[k] + wv.y * hv[k + 1] + wv.z * hv[k + 2] + wv.w * hv[k + 3];
    }
    out[b * C_ + c] = acc + fb[c];
}

// ---------------------------------------------------------------------------
extern "C" void kernel_launch(void* const* d_in, const int* in_sizes, int n_in,
                              void* d_out, int out_size)
{
    const float* x     = (const float*)d_in[0];
    const float* W_ih0 = (const float*)d_in[1];
    const float* W_hh0 = (const float*)d_in[2];
    const float* b_ih0 = (const float*)d_in[3];
    const float* b_hh0 = (const float*)d_in[4];
    const float* W_ih1 = (const float*)d_in[5];
    const float* W_hh1 = (const float*)d_in[6];
    const float* b_ih1 = (const float*)d_in[7];
    const float* b_hh1 = (const float*)d_in[8];
    const float* fc_w  = (const float*)d_in[9];
    const float* fc_b  = (const float*)d_in[10];
    float* out = (float*)d_out;

    float *bufA, *bufB;
    cudaGetSymbolAddress((void**)&bufA, g_bufA);
    cudaGetSymbolAddress((void**)&bufB, g_bufB);

    const int M = B_ * T_;
    dim3 gemm_grid(M / BM, H_ / BN);

    // pre0 = x @ W_ih0^T + b_ih0 + b_hh0
    sgemm_bias_kernel<<<gemm_grid, 256>>>(x, W_ih0, b_ih0, b_hh0, bufA,
                                          M, H_, IN_);
    // layer 0 scan: bufA(pre) -> bufB(h0)
    scan_kernel<<<dim3(16 * CLUSTER_S), SCAN_THREADS>>>(W_hh0, bufA, bufB);
    // pre1 = h0 @ W_ih1^T + b_ih1 + b_hh1
    sgemm_bias_kernel<<<gemm_grid, 256>>>(bufB, W_ih1, b_ih1, b_hh1, bufA,
                                          M, H_, H_);
    // layer 1 scan: bufA(pre) -> bufA(h1, in-place)
    scan_kernel<<<dim3(16 * CLUSTER_S), SCAN_THREADS>>>(W_hh1, bufA, bufA);
    // out = h1[:, -1, :] @ fc_w^T + fc_b
    fc_kernel<<<B_, C_>>>(bufA, fc_w, fc_b, out);
}

// round 3
// speedup vs baseline: 2.2002x; 1.2321x over previous
#include <cuda_runtime.h>

// Problem dims
#define B_  64
#define T_  2048
#define IN_ 256
#define H_  512
#define C_  128

// Scan config: 16 clusters x 8 CTAs, 4 batches/cluster, 64 H-rows/CTA
#define CLUSTER_S 8
#define JS        64      // H_/CLUSTER_S rows of W_hh per CTA
#define GBATCH    4       // batches per cluster
#define KC        8       // k-chunks per row
#define KPT       64      // k elements per thread (H_/KC)
#define SCAN_THREADS 512

// Scratch ping-pong buffers (device globals: allocation-free)
__device__ float g_bufA[(size_t)B_ * T_ * H_];
__device__ float g_bufB[(size_t)B_ * T_ * H_];

static __device__ __forceinline__ unsigned smem_u32(const void* p) {
    unsigned r;
    asm("{ .reg .u64 t; cvta.to.shared.u64 t, %1; cvt.u32.u64 %0, t; }"
        : "=r"(r) : "l"(p));
    return r;
}

// packed fp32x2 FMA: d = a*b + d
static __device__ __forceinline__ void ffma2(unsigned long long& d,
                                             unsigned long long a,
                                             unsigned long long b) {
    asm("fma.rn.f32x2 %0, %1, %2, %0;" : "+l"(d) : "l"(a), "l"(b));
}

static __device__ __forceinline__ float hadd2(unsigned long long a) {
    float lo = __uint_as_float((unsigned)(a & 0xffffffffull));
    float hi = __uint_as_float((unsigned)(a >> 32));
    return lo + hi;
}

static __device__ __forceinline__ unsigned long long dupf(float f) {
    unsigned long long r;
    asm("mov.b64 %0, {%1, %1};" : "=l"(r) : "f"(f));
    return r;
}

// ---------------------------------------------------------------------------
// Recurrent scan: h_t = relu(pre_t + W_hh @ h_{t-1}).
// 16 clusters x 8 CTAs x 512 threads. Thread (kc,j) holds
// W[rank*64+j][kc*64 .. +63] in 32 packed f32x2 registers. h double-buffered
// in SMEM; partials reduced via SMEM; h values replicated to all 8 cluster
// CTAs via st.async + mbarrier transaction accounting (no cluster barrier
// in the steady state).
// ---------------------------------------------------------------------------
__global__ void __launch_bounds__(SCAN_THREADS, 1) __cluster_dims__(CLUSTER_S, 1, 1)
scan_kernel(const float* __restrict__ W_hh, const float* __restrict__ pre,
            float* __restrict__ hout)
{
    __shared__ float Hs[2][GBATCH][H_];          // 16 KB
    __shared__ float red[KC][JS][GBATCH];        // 8 KB
    __shared__ __align__(8) unsigned long long mbar;

    const int tid  = threadIdx.x;
    const int rank = blockIdx.x & (CLUSTER_S - 1);
    const int bg   = blockIdx.x >> 3;

    // producer identity
    const int kc = tid >> 6;            // 0..7
    const int j  = tid & 63;            // 0..63
    // reducer identity (tid < 256)
    const int j2   = tid >> 2;          // 0..63
    const int b2   = tid & 3;           // 0..3
    const int jg2  = rank * JS + j2;
    const int bred = bg * GBATCH + b2;

    // W slice into registers: 32 packed f32x2 = 64 fp32
    unsigned long long w[KPT / 2];
    {
        const float* wsrc = W_hh + (size_t)(rank * JS + j) * H_ + kc * KPT;
        #pragma unroll
        for (int i = 0; i < KPT / 2; i++)
            w[i] = *reinterpret_cast<const unsigned long long*>(wsrc + 2 * i);
    }

    // h_0 = 0 in both buffers
    for (int i = tid; i < 2 * GBATCH * H_; i += SCAN_THREADS)
        (&Hs[0][0][0])[i] = 0.f;

    const unsigned mbar_l = smem_u32(&mbar);
    if (tid == 0) {
        asm volatile("mbarrier.init.shared.b64 [%0], 1;" :: "r"(mbar_l) : "memory");
    }
    // remote mbar addresses (loop-invariant)
    unsigned rmbar[CLUSTER_S];
    #pragma unroll
    for (int r = 0; r < CLUSTER_S; r++)
        asm("mapa.shared::cluster.u32 %0, %1, %2;" : "=r"(rmbar[r]) : "r"(mbar_l), "r"(r));

    // local h destination addresses (one per buffer) for this reducer's value
    const unsigned loc_h0 = smem_u32(&Hs[0][b2][jg2]);
    const unsigned loc_h1 = smem_u32(&Hs[1][b2][jg2]);

    __syncthreads();
    asm volatile("barrier.cluster.arrive.aligned;" ::: "memory");
    asm volatile("barrier.cluster.wait.aligned;"   ::: "memory");

    const float* preP  = pre  + ((size_t)bred * T_) * H_ + jg2;
    float*       houtP = hout + ((size_t)bred * T_) * H_ + jg2;

    float pv = (tid < 256) ? *preP : 0.f;   // pre for t=0
    int cur = 0;

    #pragma unroll 1
    for (int t = 0; t < T_; ++t) {
        // ---- partial dots: 4 independent acc chains, batch-interleaved loads
        const ulonglong2* hp =
            reinterpret_cast<const ulonglong2*>(&Hs[cur][0][0]) + kc * (KPT / 4);
        unsigned long long a0 = 0ull, a1 = 0ull, a2 = 0ull, a3 = 0ull;
        #pragma unroll
        for (int i = 0; i < KPT / 4; i++) {
            ulonglong2 v0 = hp[i];                    // b=0
            ulonglong2 v1 = hp[i + 128];              // b=1 (512 floats)
            ulonglong2 v2 = hp[i + 256];              // b=2
            ulonglong2 v3 = hp[i + 384];              // b=3
            ffma2(a0, w[2 * i], v0.x); ffma2(a0, w[2 * i + 1], v0.y);
            ffma2(a1, w[2 * i], v1.x); ffma2(a1, w[2 * i + 1], v1.y);
            ffma2(a2, w[2 * i], v2.x); ffma2(a2, w[2 * i + 1], v2.y);
            ffma2(a3, w[2 * i], v3.x); ffma2(a3, w[2 * i + 1], v3.y);
        }
        *reinterpret_cast<float4*>(&red[kc][j][0]) =
            make_float4(hadd2(a0), hadd2(a1), hadd2(a2), hadd2(a3));
        __syncthreads();

        const int nxt = cur ^ 1;
        if (tid == 0) {
            asm volatile("mbarrier.arrive.expect_tx.shared.b64 _, [%0], %1;"
                         :: "r"(mbar_l), "r"(8192u) : "memory");
        }
        if (tid < 256) {
            // ---- cross-kc reduction + bias + relu
            float s = red[0][j2][b2] + red[1][j2][b2]
                    + red[2][j2][b2] + red[3][j2][b2]
                    + red[4][j2][b2] + red[5][j2][b2]
                    + red[6][j2][b2] + red[7][j2][b2] + pv;
            float val = fmaxf(s, 0.f);
            unsigned uval  = __float_as_uint(val);
            unsigned loc_h = nxt ? loc_h1 : loc_h0;

            // replicate to all 8 cluster CTAs with tx accounting
            #pragma unroll
            for (int r = 0; r < CLUSTER_S; ++r) {
                unsigned rh;
                asm("mapa.shared::cluster.u32 %0, %1, %2;"
                    : "=r"(rh) : "r"(loc_h), "r"(r));
                asm volatile(
                    "st.async.shared::cluster.mbarrier::complete_tx::bytes.b32 "
                    "[%0], %1, [%2];"
                    :: "r"(rh), "r"(uval), "r"(rmbar[r]) : "memory");
            }
            // overlapped with in-flight replication
            houtP[(size_t)t * H_] = val;
            if (t + 1 < T_) pv = preP[(size_t)(t + 1) * H_];
        }

        // wait: all 8 CTAs' 2048 values (8192 B) arrived + local expect armed
        {
            const unsigned par = (unsigned)(t & 1);
            asm volatile(
                "{\n\t.reg .pred P;\n\t"
                "WAIT_%=:\n\t"
                "mbarrier.try_wait.parity.acquire.cta.shared::cta.b64 P, [%0], %1, 0x989680;\n\t"
                "@!P bra WAIT_%=;\n\t}"
                :: "r"(mbar_l), "r"(par) : "memory");
        }
        cur = nxt;
    }

    asm volatile("barrier.cluster.arrive.aligned;" ::: "memory");
    asm volatile("barrier.cluster.wait.aligned;"   ::: "memory");
}

// ---------------------------------------------------------------------------
// C[M,N] = A[M,K] @ Bw[N,K]^T + bias1[N] + bias2[N]   (fp32 tiled SGEMM)
// ---------------------------------------------------------------------------
#define BM 128
#define BN 128
#define BK 8
#define TM 8
#define TN 8

__global__ void __launch_bounds__(256)
sgemm_bias_kernel(const float* __restrict__ A, const float* __restrict__ Bw,
                  const float* __restrict__ bias1, const float* __restrict__ bias2,
                  float* __restrict__ C, int M, int N, int K)
{
    __shared__ float As[BK][BM];
    __shared__ float Bs[BK][BN];

    const int tid  = threadIdx.x;
    const int bm   = blockIdx.x * BM;
    const int bn   = blockIdx.y * BN;
    const int lrow = tid >> 1;          // 0..127
    const int lc   = (tid & 1) * 4;     // 0 or 4
    const int tx   = tid & 15;
    const int ty   = tid >> 4;

    unsigned long long acc2[TM / 2][TN];
    #pragma unroll
    for (int i = 0; i < TM / 2; i++)
        #pragma unroll
        for (int jj = 0; jj < TN; jj++) acc2[i][jj] = 0ull;

    for (int k0 = 0; k0 < K; k0 += BK) {
        float4 av = *reinterpret_cast<const float4*>(
            &A[(size_t)(bm + lrow) * K + k0 + lc]);
        float4 bv = *reinterpret_cast<const float4*>(
            &Bw[(size_t)(bn + lrow) * K + k0 + lc]);
        __syncthreads();
        As[lc + 0][lrow] = av.x; As[lc + 1][lrow] = av.y;
        As[lc + 2][lrow] = av.z; As[lc + 3][lrow] = av.w;
        Bs[lc + 0][lrow] = bv.x; Bs[lc + 1][lrow] = bv.y;
        Bs[lc + 2][lrow] = bv.z; Bs[lc + 3][lrow] = bv.w;
        __syncthreads();

        #pragma unroll
        for (int kk = 0; kk < BK; ++kk) {
            ulonglong2 raA = *reinterpret_cast<const ulonglong2*>(&As[kk][ty * TM]);
            ulonglong2 raB = *reinterpret_cast<const ulonglong2*>(&As[kk][ty * TM + 4]);
            float4 rb0 = *reinterpret_cast<const float4*>(&Bs[kk][tx * TN]);
            float4 rb1 = *reinterpret_cast<const float4*>(&Bs[kk][tx * TN + 4]);
            unsigned long long ra[4] = { raA.x, raA.y, raB.x, raB.y };
            unsigned long long rbb[8];
            rbb[0] = dupf(rb0.x); rbb[1] = dupf(rb0.y);
            rbb[2] = dupf(rb0.z); rbb[3] = dupf(rb0.w);
            rbb[4] = dupf(rb1.x); rbb[5] = dupf(rb1.y);
            rbb[6] = dupf(rb1.z); rbb[7] = dupf(rb1.w);
            #pragma unroll
            for (int i2 = 0; i2 < 4; ++i2)
                #pragma unroll
                for (int jj = 0; jj < TN; ++jj)
                    ffma2(acc2[i2][jj], ra[i2], rbb[jj]);
        }
    }

    #pragma unroll
    for (int i2 = 0; i2 < TM / 2; ++i2) {
        const size_t row0 = (size_t)(bm + ty * TM + 2 * i2) * N;
        const size_t row1 = row0 + N;
        #pragma unroll
        for (int jj = 0; jj < TN; ++jj) {
            const int col = bn + tx * TN + jj;
            float lo = __uint_as_float((unsigned)(acc2[i2][jj] & 0xffffffffull));
            float hi = __uint_as_float((unsigned)(acc2[i2][jj] >> 32));
            float bsum = bias1[col] + bias2[col];
            C[row0 + col] = lo + bsum;
            C[row1 + col] = hi + bsum;
        }
    }
}

// ---------------------------------------------------------------------------
// out[b,c] = h1[b, T-1, :] . fc_w[c, :] + fc_b[c]
// ---------------------------------------------------------------------------
__global__ void __launch_bounds__(C_)
fc_kernel(const float* __restrict__ h, const float* __restrict__ fw,
          const float* __restrict__ fb, float* __restrict__ out)
{
    __shared__ float hv[H_];
    const int b = blockIdx.x;
    const int c = threadIdx.x;
    for (int k = c; k < H_; k += C_)
        hv[k] = h[((size_t)b * T_ + (T_ - 1)) * H_ + k];
    __syncthreads();

    const float* w = fw + (size_t)c * H_;
    float acc = 0.f;
    #pragma unroll 8
    for (int k = 0; k < H_; k += 4) {
        float4 wv = *reinterpret_cast<const float4*>(w + k);
        acc += wv.x * hv[k] + wv.y * hv[k + 1] + wv.z * hv[k + 2] + wv.w * hv[k + 3];
    }
    out[b * C_ + c] = acc + fb[c];
}

// ---------------------------------------------------------------------------
extern "C" void kernel_launch(void* const* d_in, const int* in_sizes, int n_in,
                              void* d_out, int out_size)
{
    const float* x     = (const float*)d_in[0];
    const float* W_ih0 = (const float*)d_in[1];
    const float* W_hh0 = (const float*)d_in[2];
    const float* b_ih0 = (const float*)d_in[3];
    const float* b_hh0 = (const float*)d_in[4];
    const float* W_ih1 = (const float*)d_in[5];
    const float* W_hh1 = (const float*)d_in[6];
    const float* b_ih1 = (const float*)d_in[7];
    const float* b_hh1 = (const float*)d_in[8];
    const float* fc_w  = (const float*)d_in[9];
    const float* fc_b  = (const float*)d_in[10];
    float* out = (float*)d_out;

    float *bufA, *bufB;
    cudaGetSymbolAddress((void**)&bufA, g_bufA);
    cudaGetSymbolAddress((void**)&bufB, g_bufB);

    const int M = B_ * T_;
    dim3 gemm_grid(M / BM, H_ / BN);

    // pre0 = x @ W_ih0^T + b_ih0 + b_hh0
    sgemm_bias_kernel<<<gemm_grid, 256>>>(x, W_ih0, b_ih0, b_hh0, bufA,
                                          M, H_, IN_);
    // layer 0 scan: bufA(pre) -> bufB(h0)
    scan_kernel<<<dim3(16 * CLUSTER_S), SCAN_THREADS>>>(W_hh0, bufA, bufB);
    // pre1 = h0 @ W_ih1^T + b_ih1 + b_hh1
    sgemm_bias_kernel<<<gemm_grid, 256>>>(bufB, W_ih1, b_ih1, b_hh1, bufA,
                                          M, H_, H_);
    // layer 1 scan: bufA(pre) -> bufA(h1, in-place)
    scan_kernel<<<dim3(16 * CLUSTER_S), SCAN_THREADS>>>(W_hh1, bufA, bufA);
    // out = h1[:, -1, :] @ fc_w^T + fc_b
    fc_kernel<<<B_, C_>>>(bufA, fc_w, fc_b, out);
}